// round 3
// baseline (speedup 1.0000x reference)
#include <cuda_runtime.h>

#define BB 32
#define TT 2048
#define DD 512
#define D4 (DD / 4)       // 128 float4 lanes per row
#define TCHUNK 128
#define NTCH (TT / TCHUNK) // 16

__device__ float  g_sum_p[BB * DD];
__device__ float  g_sum_t[BB * DD];
__device__ double g_word;

__device__ __forceinline__ float smooth_l1f(float d) {
    float ad = fabsf(d);
    return (ad < 1.0f) ? 0.5f * d * d : ad - 0.5f;
}

__global__ void zero_kernel() {
    int i = blockIdx.x * blockDim.x + threadIdx.x;
    if (i < BB * DD) {
        g_sum_p[i] = 0.0f;
        g_sum_t[i] = 0.0f;
    }
    if (i == 0) g_word = 0.0;
}

// grid: (NTCH, BB), block: 256 threads = 128 float4 d-lanes x 2 t-offsets
__global__ void __launch_bounds__(256) main_kernel(
    const float4* __restrict__ preds,
    const float4* __restrict__ tgts,
    const int* __restrict__ lens)
{
    int b   = blockIdx.y;
    int len = lens[b];
    int t0  = blockIdx.x * TCHUNK;

    float wsum = 0.0f;

    if (t0 < len) {
        int tend = min(t0 + TCHUNK, len);
        int dv   = threadIdx.x & (D4 - 1);
        int toff = threadIdx.x >> 7;

        float4 sp = make_float4(0.f, 0.f, 0.f, 0.f);
        float4 st = make_float4(0.f, 0.f, 0.f, 0.f);

        size_t base = (size_t)b * TT * D4 + dv;
        #pragma unroll 4
        for (int t = t0 + toff; t < tend; t += 2) {
            float4 p = __ldg(&preds[base + (size_t)t * D4]);
            float4 q = __ldg(&tgts [base + (size_t)t * D4]);
            sp.x += p.x; sp.y += p.y; sp.z += p.z; sp.w += p.w;
            st.x += q.x; st.y += q.y; st.z += q.z; st.w += q.w;
            wsum += smooth_l1f(p.x - q.x);
            wsum += smooth_l1f(p.y - q.y);
            wsum += smooth_l1f(p.z - q.z);
            wsum += smooth_l1f(p.w - q.w);
        }

        float* gp = &g_sum_p[b * DD + dv * 4];
        float* gt = &g_sum_t[b * DD + dv * 4];
        atomicAdd(gp + 0, sp.x); atomicAdd(gp + 1, sp.y);
        atomicAdd(gp + 2, sp.z); atomicAdd(gp + 3, sp.w);
        atomicAdd(gt + 0, st.x); atomicAdd(gt + 1, st.y);
        atomicAdd(gt + 2, st.z); atomicAdd(gt + 3, st.w);
    }

    // block reduce wsum (all 256 threads participate, inactive blocks returned)
    __shared__ float sh[256];
    sh[threadIdx.x] = wsum;
    __syncthreads();
    for (int s = 128; s > 0; s >>= 1) {
        if (threadIdx.x < s) sh[threadIdx.x] += sh[threadIdx.x + s];
        __syncthreads();
    }
    if (threadIdx.x == 0 && sh[0] != 0.0f)
        atomicAdd(&g_word, (double)sh[0]);
}

__global__ void __launch_bounds__(256) final_kernel(
    const int* __restrict__ lens, float* __restrict__ out)
{
    __shared__ double sh[256];
    double s = 0.0;
    for (int i = threadIdx.x; i < BB * DD; i += 256) {
        int b = i >> 9; // i / DD
        float invl = 1.0f / (float)lens[b];
        float d = (g_sum_p[i] - g_sum_t[i]) * invl;
        s += (double)smooth_l1f(d);
    }
    sh[threadIdx.x] = s;
    __syncthreads();
    for (int st = 128; st > 0; st >>= 1) {
        if (threadIdx.x < st) sh[threadIdx.x] += sh[threadIdx.x + st];
        __syncthreads();
    }
    if (threadIdx.x == 0) {
        double nvalid = 0.0;
        for (int b = 0; b < BB; b++) nvalid += (double)lens[b];
        nvalid *= (double)DD;
        double word = g_word / nvalid;
        double sentence = sh[0] / (double)(DD * BB); // sum/D per b, /B at the end
        out[0] = (float)(word + sentence);
    }
}

extern "C" void kernel_launch(void* const* d_in, const int* in_sizes, int n_in,
                              void* d_out, int out_size) {
    const float4* preds = (const float4*)d_in[0];
    const float4* tgts  = (const float4*)d_in[1];
    const int*    lens  = (const int*)d_in[2];
    float*        out   = (float*)d_out;

    zero_kernel<<<(BB * DD + 255) / 256, 256>>>();
    dim3 grid(NTCH, BB);
    main_kernel<<<grid, 256>>>(preds, tgts, lens);
    final_kernel<<<1, 256>>>(lens, out);
}

// round 9
// speedup vs baseline: 1.7700x; 1.7700x over previous
#include <cuda_runtime.h>

#define BB 32
#define TT 2048
#define DD 512
#define D4 128            // DD/4 float4 lanes
#define TCH 64            // timesteps per chunk
#define NCH 32            // TT/TCH

// Partial sums: [b][chunk][d4] as float4. 2 MB each.
__device__ float4 g_pp[BB * NCH * D4];
__device__ float4 g_pt[BB * NCH * D4];
__device__ float  g_wpart[BB * NCH];     // word-loss partial per (b,chunk)
__device__ double g_sent_part[BB];       // per-k2-block sentence partials

__device__ __forceinline__ float smooth_l1f(float d) {
    float ad = fabsf(d);
    return (ad < 1.0f) ? 0.5f * d * d : ad - 0.5f;
}

// grid (NCH, BB), 128 threads: thread = one float4 d-lane, loops over 64 t.
__global__ void __launch_bounds__(128) k1_partials(
    const float4* __restrict__ preds,
    const float4* __restrict__ tgts,
    const int* __restrict__ lens)
{
    const int c = blockIdx.x, b = blockIdx.y;
    const int len = lens[b];
    const int t0  = c * TCH;
    if (t0 >= len) return;                 // inactive chunk: zero work
    const int tend = min(t0 + TCH, len);
    const int dv = threadIdx.x;

    float4 sp = make_float4(0.f, 0.f, 0.f, 0.f);
    float4 st = make_float4(0.f, 0.f, 0.f, 0.f);
    float  w  = 0.f;

    const size_t base = (size_t)b * TT * D4 + dv;
    #pragma unroll 4
    for (int t = t0; t < tend; ++t) {
        float4 a = __ldg(&preds[base + (size_t)t * D4]);
        float4 r = __ldg(&tgts [base + (size_t)t * D4]);
        sp.x += a.x; sp.y += a.y; sp.z += a.z; sp.w += a.w;
        st.x += r.x; st.y += r.y; st.z += r.z; st.w += r.w;
        w += smooth_l1f(a.x - r.x);
        w += smooth_l1f(a.y - r.y);
        w += smooth_l1f(a.z - r.z);
        w += smooth_l1f(a.w - r.w);
    }

    const int idx = (b * NCH + c) * D4 + dv;
    g_pp[idx] = sp;
    g_pt[idx] = st;

    // block-reduce w (4 warps)
    #pragma unroll
    for (int o = 16; o > 0; o >>= 1) w += __shfl_down_sync(0xffffffffu, w, o);
    __shared__ float sh[4];
    if ((threadIdx.x & 31) == 0) sh[threadIdx.x >> 5] = w;
    __syncthreads();
    if (threadIdx.x == 0) g_wpart[b * NCH + c] = sh[0] + sh[1] + sh[2] + sh[3];
}

// grid: exactly BB blocks x 128 threads. Block bi handles b = bi (128 d4 lanes).
__global__ void __launch_bounds__(128) k2_sentence(const int* __restrict__ lens)
{
    const int b  = blockIdx.x;        // 0..BB-1
    const int dv = threadIdx.x;       // 0..127
    const int len = lens[b];
    const int nc = (len + TCH - 1) / TCH;

    float4 sp = make_float4(0.f, 0.f, 0.f, 0.f);
    float4 st = make_float4(0.f, 0.f, 0.f, 0.f);
    const int base = b * NCH * D4 + dv;
    for (int c = 0; c < nc; ++c) {
        float4 a = g_pp[base + c * D4];
        float4 r = g_pt[base + c * D4];
        sp.x += a.x; sp.y += a.y; sp.z += a.z; sp.w += a.w;
        st.x += r.x; st.y += r.y; st.z += r.z; st.w += r.w;
    }
    const float invl = 1.0f / (float)len;
    double s = (double)smooth_l1f((sp.x - st.x) * invl)
             + (double)smooth_l1f((sp.y - st.y) * invl)
             + (double)smooth_l1f((sp.z - st.z) * invl)
             + (double)smooth_l1f((sp.w - st.w) * invl);

    // block-reduce double (4 warps)
    #pragma unroll
    for (int o = 16; o > 0; o >>= 1) s += __shfl_down_sync(0xffffffffu, s, o);
    __shared__ double sh[4];
    if ((threadIdx.x & 31) == 0) sh[threadIdx.x >> 5] = s;
    __syncthreads();
    if (threadIdx.x == 0)
        g_sent_part[b] = sh[0] + sh[1] + sh[2] + sh[3];
}

// 1 block: fold word partials + sentence partials + final scalar combine.
__global__ void __launch_bounds__(256) k3_final(const int* __restrict__ lens,
                                                float* __restrict__ out)
{
    __shared__ double sh[256];
    const int tid = threadIdx.x;
    double w = 0.0;
    for (int i = tid; i < BB * NCH; i += 256) {
        int b = i >> 5, c = i & 31;
        if (c * TCH < lens[b]) w += (double)g_wpart[i];
    }
    sh[tid] = w;
    __syncthreads();
    for (int s = 128; s > 0; s >>= 1) {
        if (tid < s) sh[tid] += sh[tid + s];
        __syncthreads();
    }
    if (tid == 0) {
        double sent = 0.0, nvalid = 0.0;
        for (int b = 0; b < BB; ++b) {
            sent   += g_sent_part[b];
            nvalid += (double)lens[b];
        }
        nvalid *= (double)DD;
        out[0] = (float)(sh[0] / nvalid + sent / (double)(DD * BB));
    }
}

extern "C" void kernel_launch(void* const* d_in, const int* in_sizes, int n_in,
                              void* d_out, int out_size) {
    const float4* preds = (const float4*)d_in[0];
    const float4* tgts  = (const float4*)d_in[1];
    const int*    lens  = (const int*)d_in[2];
    float*        out   = (float*)d_out;

    dim3 g1(NCH, BB);
    k1_partials<<<g1, 128>>>(preds, tgts, lens);
    k2_sentence<<<BB, 128>>>(lens);
    k3_final<<<1, 256>>>(lens, out);
}